// round 12
// baseline (speedup 1.0000x reference)
#include <cuda_runtime.h>
#include <cuda_fp16.h>
#include <math.h>
#include <stdint.h>

#define N_FR   16384
#define D_EMB  1024
#define A_DIM  2048
#define H_H    8
#define B_SEG  64
#define DH     (D_EMB*H_H)
#define NTA    16         // a-tiles of 128
#define PSPL   16         // pool row-splits

// ---------------- scratch ---------------------------------------------------
__device__ __align__(128) __half g_xh [N_FR*D_EMB];            // x in fp16
__device__ __align__(128) __half g_w1h[A_DIM*D_EMB];           // w1^T hi fp16
__device__ __align__(128) __half g_w1l[A_DIM*D_EMB];           // w1^T lo fp16
__device__ float g_hpart[NTA][N_FR*H_H];
__device__ float g_h[N_FR*H_H];
__device__ float g_attn[N_FR*H_H];
__device__ float g_obdh[B_SEG*DH];
__device__ float g_poolpart[PSPL][B_SEG*DH];
__device__ float g_msumpart[PSPL][B_SEG*D_EMB];
__device__ float g_outpart[8][B_SEG*D_EMB];
__device__ int   g_segstart[B_SEG+1];

// ---------------- helpers ----------------------------------------------------
__device__ __forceinline__ uint32_t smem_u32(const void* p){
    uint32_t a;
    asm("{ .reg .u64 t; cvta.to.shared.u64 t, %1; cvt.u32.u64 %0, t; }" : "=r"(a) : "l"(p));
    return a;
}
__device__ __forceinline__ void cpa16(uint32_t dst, const void* src){
    asm volatile("cp.async.cg.shared.global [%0], [%1], 16;\n" :: "r"(dst), "l"(src));
}
__device__ __forceinline__ void cpa_commit(){ asm volatile("cp.async.commit_group;\n" ::: "memory"); }
__device__ __forceinline__ void cpa_wait0(){ asm volatile("cp.async.wait_group 0;\n" ::: "memory"); }

__device__ __forceinline__ void ldm_x4(uint32_t* r, uint32_t addr){
    asm volatile("ldmatrix.sync.aligned.m8n8.x4.shared.b16 {%0,%1,%2,%3}, [%4];"
        : "=r"(r[0]),"=r"(r[1]),"=r"(r[2]),"=r"(r[3]) : "r"(addr));
}
__device__ __forceinline__ void mma_f16(float* d, const uint32_t* a, const uint32_t* b){
    asm volatile("mma.sync.aligned.m16n8k16.row.col.f32.f16.f16.f32 "
        "{%0,%1,%2,%3}, {%4,%5,%6,%7}, {%8,%9}, {%0,%1,%2,%3};"
        : "+f"(d[0]),"+f"(d[1]),"+f"(d[2]),"+f"(d[3])
        : "r"(a[0]),"r"(a[1]),"r"(a[2]),"r"(a[3]), "r"(b[0]),"r"(b[1]));
}

// ---------------- 0: prefix sum ---------------------------------------------
__global__ void k_prefix(const int* __restrict__ seg){
    if (threadIdx.x == 0){
        int acc = 0; g_segstart[0] = 0;
        for (int i = 0; i < B_SEG; i++){ acc += seg[i]; g_segstart[i+1] = acc; }
    }
}

// ---------------- 1a: x -> fp16 ------------------------------------------------
__global__ __launch_bounds__(256) void k_splitx(const float* __restrict__ x){
    size_t i = ((size_t)blockIdx.x * 256 + threadIdx.x) * 4;
    float4 v = *(const float4*)(x + i);
    *(__half2*)&g_xh[i]   = __floats2half2_rn(v.x, v.y);
    *(__half2*)&g_xh[i+2] = __floats2half2_rn(v.z, v.w);
}

// ---------------- 1b: transpose + fp16 hi/lo split of w1 -----------------------
__global__ void k_splitw(const float* __restrict__ w1){
    __shared__ float t[32][33];
    int a0 = blockIdx.x * 32, k0 = blockIdx.y * 32;
    int tx = threadIdx.x, ty = threadIdx.y;   // (32, 8)
    #pragma unroll
    for (int i = 0; i < 4; i++)
        t[ty + i*8][tx] = w1[(size_t)(k0 + ty + i*8) * A_DIM + a0 + tx];
    __syncthreads();
    #pragma unroll
    for (int i = 0; i < 4; i++){
        int al = ty + i*8;
        float v = t[tx][al];
        __half h = __float2half_rn(v);
        g_w1h[(size_t)(a0 + al) * D_EMB + k0 + tx] = h;
        g_w1l[(size_t)(a0 + al) * D_EMB + k0 + tx] =
            __float2half_rn(v - __half2float(h));
    }
}

// ---------------- 2: fp16x2 MMA GEMM + fused relu@w2 epilogue ------------------
// CTA 128m x 128a, 8 warps (2x4), warp tile 64x32, K chunks of 32.
// 64B rows, XOR swizzle s(r)=(r>>1)&3 (conflict-free LDSM).
// 4-stage buffers, PAIRED chunks: 1 wait + 1 sync per 2 chunks; loads for the
// next pair issued right after the sync (buffers provably drained).
#define ROWB   64                 // row stride in bytes (32 fp16, swizzled)
#define ARR_SZ (128*ROWB)         // 8192 B per operand array
#define STG_SZ (3*ARR_SZ)         // XH|WH|WL = 24576 B
#define NSTG   4
#define OFF_XH 0
#define OFF_WH (1*ARR_SZ)
#define OFF_WL (2*ARR_SZ)
#define OFF_C  0                            // union with stage buffers
#define C_LD   136                          // fp32 words per C row (128+8 pad)
#define OFF_W2 (NSTG*STG_SZ)                // 98304
#define SM_TOT (OFF_W2 + 128*H_H*4)         // 102400

__device__ __forceinline__ uint32_t swz(int row, int j){
    return (uint32_t)(row * ROWB + ((j ^ ((row >> 1) & 3)) << 4));
}

__device__ __forceinline__ void load_chunk(uint32_t sbuf, int c, int m0, int a0){
    const int tid = threadIdx.x;
    const int row = tid >> 1;
    const int j0  = (tid & 1) * 2;          // 16B chunks j0, j0+1
    const size_t xo = (size_t)(m0 + row) * D_EMB + c * 32;
    const size_t wo = (size_t)(a0 + row) * D_EMB + c * 32;
    #pragma unroll
    for (int j = j0; j < j0 + 2; j++){
        const uint32_t so = swz(row, j);
        cpa16(sbuf + OFF_XH + so, g_xh  + xo + j * 8);
        cpa16(sbuf + OFF_WH + so, g_w1h + wo + j * 8);
        cpa16(sbuf + OFF_WL + so, g_w1l + wo + j * 8);
    }
    cpa_commit();
}

struct LaneCtx { int a_row, a_jh, b_row, b_jh, wm, wn; };

__device__ __forceinline__ void do_k16(uint32_t base, const LaneCtx& L, int kk,
                                       float acc[4][4][4]){
    const int jb = kk * 2;
    uint32_t ah[4][4];
    #pragma unroll
    for (int mt = 0; mt < 4; mt++){
        int r = L.wm * 64 + mt * 16 + L.a_row;
        ldm_x4(ah[mt], base + OFF_XH + swz(r, jb + L.a_jh));
    }
    uint32_t bh[2][4], bl[2][4];    // [np][4]: {n0k0,n0k8,n1k0,n1k8}
    #pragma unroll
    for (int np = 0; np < 2; np++){
        int r = L.wn * 32 + np * 16 + L.b_row;
        ldm_x4(bh[np], base + OFF_WH + swz(r, jb + L.b_jh));
    }
    #pragma unroll
    for (int np = 0; np < 2; np++){
        int r = L.wn * 32 + np * 16 + L.b_row;
        ldm_x4(bl[np], base + OFF_WL + swz(r, jb + L.b_jh));
    }
    #pragma unroll
    for (int mt = 0; mt < 4; mt++)
        #pragma unroll
        for (int nt = 0; nt < 4; nt++)
            mma_f16(acc[mt][nt], ah[mt], &bh[nt >> 1][(nt & 1) * 2]);
    #pragma unroll
    for (int mt = 0; mt < 4; mt++)
        #pragma unroll
        for (int nt = 0; nt < 4; nt++)
            mma_f16(acc[mt][nt], ah[mt], &bl[nt >> 1][(nt & 1) * 2]);
}

__global__ void __launch_bounds__(256, 2) k_mma1(const float* __restrict__ w2){
    extern __shared__ char smem[];
    const uint32_t sb = smem_u32(smem);
    float* Cs  = (float*)(smem + OFF_C);
    float* W2s = (float*)(smem + OFF_W2);
    const int tid = threadIdx.x;
    const int wid = tid >> 5, lane = tid & 31;
    const int grp = lane >> 2, t4 = lane & 3;
    const int m0 = blockIdx.x * 128;
    const int a0 = blockIdx.y * 128;
    const int kk0 = wid & 1;                 // warp de-phasing

    LaneCtx L;
    L.wm = wid >> 2; L.wn = wid & 3;
    L.a_row = (lane & 15);
    L.a_jh  = (lane >> 4);
    L.b_row = (lane & 7) + ((lane >> 4) << 3);
    L.b_jh  = ((lane >> 3) & 1);

    for (int i = tid; i < 128 * H_H; i += 256)
        W2s[i] = w2[(size_t)(a0 + (i >> 3)) * H_H + (i & 7)];

    float acc[4][4][4];
    #pragma unroll
    for (int mt = 0; mt < 4; mt++)
        #pragma unroll
        for (int nt = 0; nt < 4; nt++)
            #pragma unroll
            for (int j = 0; j < 4; j++) acc[mt][nt][j] = 0.f;

    // preload pair (0,1), separate commit groups
    load_chunk(sb + 0*STG_SZ, 0, m0, a0);
    load_chunk(sb + 1*STG_SZ, 1, m0, a0);

    for (int cp = 0; cp < 16; cp++){
        const int c = cp * 2;
        cpa_wait0();                 // only this pair's groups are outstanding
        __syncthreads();             // everyone done with pair (c-2, c-1) buffers
        if (c + 2 < 32){             // loads overlap both chunks' MMA work
            load_chunk(sb + ((c + 2) & 3) * STG_SZ, c + 2, m0, a0);
            load_chunk(sb + ((c + 3) & 3) * STG_SZ, c + 3, m0, a0);
        }
        const uint32_t base0 = sb + ( c      & 3) * STG_SZ;
        const uint32_t base1 = sb + ((c + 1) & 3) * STG_SZ;
        do_k16(base0, L, kk0, acc);
        do_k16(base0, L, kk0 ^ 1, acc);
        do_k16(base1, L, kk0, acc);
        do_k16(base1, L, kk0 ^ 1, acc);
    }
    __syncthreads();   // all warps done reading buffers before C overwrites them

    // relu(C) -> smem (union region)
    #pragma unroll
    for (int mt = 0; mt < 4; mt++)
        #pragma unroll
        for (int nt = 0; nt < 4; nt++){
            const int r0 = L.wm * 64 + mt * 16 + grp;
            const int c0 = L.wn * 32 + nt * 8 + t4 * 2;
            Cs[(r0    ) * C_LD + c0    ] = fmaxf(acc[mt][nt][0], 0.f);
            Cs[(r0    ) * C_LD + c0 + 1] = fmaxf(acc[mt][nt][1], 0.f);
            Cs[(r0 + 8) * C_LD + c0    ] = fmaxf(acc[mt][nt][2], 0.f);
            Cs[(r0 + 8) * C_LD + c0 + 1] = fmaxf(acc[mt][nt][3], 0.f);
        }
    __syncthreads();

    // h partial: relu(C)[128x128] @ w2slice[128x8]
    #pragma unroll
    for (int it = 0; it < 4; it++){
        const int idx = tid + it * 256;
        const int row = idx >> 3, h = idx & 7;
        float s = 0.f;
        #pragma unroll 8
        for (int cc = 0; cc < 128; cc++)
            s = fmaf(Cs[row * C_LD + cc], W2s[cc * H_H + h], s);
        g_hpart[blockIdx.y][(size_t)(m0 + row) * H_H + h] = s;
    }
}

// ---------------- 3a: parallel reduce of h partials ----------------------------
__global__ __launch_bounds__(256) void k_hred(){
    const int i = blockIdx.x * 256 + threadIdx.x;   // N_FR*H_H = 131072
    float v = 0.f;
    #pragma unroll
    for (int p = 0; p < NTA; p++) v += g_hpart[p][i];
    g_h[i] = v;
}

// ---------------- 3b: per-segment softmax (reads combined g_h) -----------------
__global__ __launch_bounds__(256) void k_softmax(){
    const int b = blockIdx.x, tid = threadIdx.x;
    const int start = g_segstart[b];
    const int len = g_segstart[b+1] - start;
    __shared__ float red[256 * H_H];
    __shared__ float mval[H_H], sval[H_H];

    float lm[H_H];
    #pragma unroll
    for (int h = 0; h < H_H; h++) lm[h] = -1e30f;
    for (int r = tid; r < len; r += 256){
        const int n = start + r;
        #pragma unroll
        for (int h = 0; h < H_H; h++)
            lm[h] = fmaxf(lm[h], g_h[(size_t)n*H_H + h]);
    }
    #pragma unroll
    for (int h = 0; h < H_H; h++) red[tid*H_H + h] = lm[h];
    __syncthreads();
    for (int off = 128; off > 0; off >>= 1){
        if (tid < off)
            #pragma unroll
            for (int h = 0; h < H_H; h++)
                red[tid*H_H+h] = fmaxf(red[tid*H_H+h], red[(tid+off)*H_H+h]);
        __syncthreads();
    }
    if (tid < H_H) mval[tid] = red[tid];
    __syncthreads();

    float ls[H_H];
    #pragma unroll
    for (int h = 0; h < H_H; h++) ls[h] = 0.f;
    for (int r = tid; r < len; r += 256){
        const int n = start + r;
        #pragma unroll
        for (int h = 0; h < H_H; h++) ls[h] += expf(g_h[(size_t)n*H_H+h] - mval[h]);
    }
    #pragma unroll
    for (int h = 0; h < H_H; h++) red[tid*H_H + h] = ls[h];
    __syncthreads();
    for (int off = 128; off > 0; off >>= 1){
        if (tid < off)
            #pragma unroll
            for (int h = 0; h < H_H; h++)
                red[tid*H_H+h] += red[(tid+off)*H_H+h];
        __syncthreads();
    }
    if (tid < H_H) sval[tid] = red[tid];
    __syncthreads();

    float inv[H_H];
    #pragma unroll
    for (int h = 0; h < H_H; h++) inv[h] = 1.f / sval[h];
    for (int r = tid; r < len; r += 256){
        const int n = start + r;
        #pragma unroll
        for (int h = 0; h < H_H; h++)
            g_attn[(size_t)n*H_H+h] = expf(g_h[(size_t)n*H_H+h] - mval[h]) * inv[h];
    }
}

// ---------------- 4: pooling (reads fp16 x, column pairs) -----------------------
__global__ __launch_bounds__(256) void k_pool(){
    const int b = blockIdx.x;
    const int d0 = blockIdx.y * 512 + threadIdx.x * 2;
    const int chunk = blockIdx.z;
    const int start = g_segstart[b];
    const int len = g_segstart[b+1] - start;
    const int cl = (len + PSPL - 1) / PSPL;
    const int r0b = chunk * cl;
    const int r1b = min(len, r0b + cl);

    __shared__ float sat[32][H_H];
    float2 acc[H_H];
    #pragma unroll
    for (int h = 0; h < H_H; h++) acc[h] = make_float2(0.f, 0.f);
    float2 ssum = make_float2(0.f, 0.f);

    for (int r0 = r0b; r0 < r1b; r0 += 32){
        const int cnt = min(32, r1b - r0);
        if (threadIdx.x < cnt * H_H){
            const int rr = threadIdx.x >> 3, hh = threadIdx.x & 7;
            sat[rr][hh] = g_attn[(size_t)(start + r0 + rr) * H_H + hh];
        }
        __syncthreads();
        for (int rr = 0; rr < cnt; rr++){
            __half2 xv2 = *(const __half2*)&g_xh[(size_t)(start + r0 + rr) * D_EMB + d0];
            float2 xf = __half22float2(xv2);
            ssum.x += xf.x; ssum.y += xf.y;
            #pragma unroll
            for (int h = 0; h < H_H; h++){
                acc[h].x = fmaf(xf.x, sat[rr][h], acc[h].x);
                acc[h].y = fmaf(xf.y, sat[rr][h], acc[h].y);
            }
        }
        __syncthreads();
    }
    #pragma unroll
    for (int h = 0; h < H_H; h++){
        g_poolpart[chunk][(size_t)b * DH + d0 * H_H + h]       = acc[h].x;
        g_poolpart[chunk][(size_t)b * DH + (d0 + 1) * H_H + h] = acc[h].y;
    }
    g_msumpart[chunk][(size_t)b * D_EMB + d0]     = ssum.x;
    g_msumpart[chunk][(size_t)b * D_EMB + d0 + 1] = ssum.y;
}

__global__ __launch_bounds__(256) void k_poolred(float* __restrict__ out){
    const int i = blockIdx.x * 256 + threadIdx.x;   // 65536
    const int b = i >> 10, d = i & 1023;
    float acc[H_H];
    #pragma unroll
    for (int h = 0; h < H_H; h++) acc[h] = 0.f;
    float s = 0.f;
    #pragma unroll
    for (int p = 0; p < PSPL; p++){
        #pragma unroll
        for (int h = 0; h < H_H; h++)
            acc[h] += g_poolpart[p][(size_t)b * DH + d * H_H + h];
        s += g_msumpart[p][(size_t)b * D_EMB + d];
    }
    #pragma unroll
    for (int h = 0; h < H_H; h++)
        g_obdh[(size_t)b * DH + d * H_H + h] = acc[h];
    const int len = g_segstart[b+1] - g_segstart[b];
    out[B_SEG * D_EMB + i] = s / (float)len;
}

// ---------------- 5: attn gram (4-way row split + smem reduce) ------------------
__global__ __launch_bounds__(256) void k_gram(float* __restrict__ out){
    const int b = blockIdx.x, tid = threadIdx.x;
    const int pair = tid & 63;          // (i,j)
    const int slice = tid >> 6;         // 0..3
    const int i = pair >> 3, j = pair & 7;
    const int start = g_segstart[b];
    const int len = g_segstart[b+1] - start;
    const int cl = (len + 3) >> 2;
    const int r0 = slice * cl;
    const int r1 = min(len, r0 + cl);
    float acc = 0.f;
    for (int r = r0; r < r1; r++){
        const float* a = &g_attn[(size_t)(start + r) * H_H];
        acc = fmaf(a[i], a[j], acc);
    }
    __shared__ float red[256];
    red[tid] = acc;
    __syncthreads();
    if (tid < 128) red[tid] += red[tid + 128];
    __syncthreads();
    if (tid < 64)
        out[2 * B_SEG * D_EMB + b * 64 + tid] = red[tid] + red[tid + 64];
}

// ---------------- 6: post GEMM (64x1024x8192) -----------------------------------
__global__ __launch_bounds__(256) void k_post(const float* __restrict__ wp){
    __shared__ float As[16][72];
    __shared__ float Ws[16][72];
    const int tid = threadIdx.x;
    const int tx = tid & 15, ty = tid >> 4;
    const int j0 = blockIdx.x * 64;
    const int ks = blockIdx.y;
    const int kbase = ks * 1024;

    float acc[4][4];
    #pragma unroll
    for (int i = 0; i < 4; i++)
        #pragma unroll
        for (int j = 0; j < 4; j++) acc[i][j] = 0.f;

    for (int kc = 0; kc < 64; kc++){
        const int k0 = kbase + kc * 16;
        {
            const int row = tid >> 2, q = tid & 3;
            float4 v = *(const float4*)&g_obdh[(size_t)row * DH + k0 + q * 4];
            As[q*4+0][row] = v.x; As[q*4+1][row] = v.y;
            As[q*4+2][row] = v.z; As[q*4+3][row] = v.w;
        }
        {
            const int row = tid >> 4, q = tid & 15;
            float4 v = *(const float4*)&wp[(size_t)(k0 + row) * D_EMB + j0 + q * 4];
            *(float4*)&Ws[row][q * 4] = v;
        }
        __syncthreads();
        #pragma unroll
        for (int k = 0; k < 16; k++){
            float4 av = *(const float4*)&As[k][ty * 4];
            float4 wv = *(const float4*)&Ws[k][tx * 4];
            float ar[4] = {av.x, av.y, av.z, av.w};
            float wr[4] = {wv.x, wv.y, wv.z, wv.w};
            #pragma unroll
            for (int i = 0; i < 4; i++)
                #pragma unroll
                for (int j = 0; j < 4; j++)
                    acc[i][j] = fmaf(ar[i], wr[j], acc[i][j]);
        }
        __syncthreads();
    }
    #pragma unroll
    for (int i = 0; i < 4; i++)
        #pragma unroll
        for (int j = 0; j < 4; j++)
            g_outpart[ks][(size_t)(ty*4 + i) * D_EMB + j0 + tx*4 + j] = acc[i][j];
}

__global__ void k_redout(float* __restrict__ out){
    const int i = blockIdx.x * 256 + threadIdx.x;
    float s = 0.f;
    #pragma unroll
    for (int p = 0; p < 8; p++) s += g_outpart[p][i];
    out[i] = s;
}

// ---------------- launch ----------------------------------------------------------
extern "C" void kernel_launch(void* const* d_in, const int* in_sizes, int n_in,
                              void* d_out, int out_size)
{
    const float* x   = (const float*)d_in[0];
    const int*   seg = (const int*)  d_in[1];
    const float* w1  = (const float*)d_in[2];
    const float* w2  = (const float*)d_in[3];
    const float* wp  = (const float*)d_in[4];
    float* out = (float*)d_out;

    cudaFuncSetAttribute(k_mma1, cudaFuncAttributeMaxDynamicSharedMemorySize, SM_TOT);

    k_prefix  <<<1, 32>>>(seg);
    k_splitx  <<<N_FR*D_EMB/1024, 256>>>(x);
    k_splitw  <<<dim3(A_DIM/32, D_EMB/32), dim3(32, 8)>>>(w1);
    k_mma1    <<<dim3(N_FR/128, NTA), 256, SM_TOT>>>(w2);
    k_hred    <<<N_FR*H_H/256, 256>>>();
    k_softmax <<<B_SEG, 256>>>();
    k_pool    <<<dim3(B_SEG, 2, PSPL), 256>>>();
    k_poolred <<<B_SEG*D_EMB/256, 256>>>(out);
    k_gram    <<<B_SEG, 256>>>(out);
    k_post    <<<dim3(16, 8), 256>>>(wp);
    k_redout  <<<B_SEG*D_EMB/256, 256>>>(out);
}

// round 13
// speedup vs baseline: 1.1501x; 1.1501x over previous
#include <cuda_runtime.h>
#include <cuda_fp16.h>
#include <math.h>
#include <stdint.h>

#define N_FR   16384
#define D_EMB  1024
#define A_DIM  2048
#define H_H    8
#define B_SEG  64
#define DH     (D_EMB*H_H)
#define NTA    16         // a-tiles of 128
#define PSPL   16         // pool row-splits

// ---------------- scratch ---------------------------------------------------
__device__ __align__(128) __half g_xh [N_FR*D_EMB];            // x in fp16
__device__ __align__(128) __half g_w1h[A_DIM*D_EMB];           // w1^T hi fp16
__device__ __align__(128) __half g_w1l[A_DIM*D_EMB];           // w1^T lo fp16
__device__ float g_hpart[NTA][N_FR*H_H];
__device__ float g_h[N_FR*H_H];
__device__ float g_attn[N_FR*H_H];
__device__ float g_obdh[B_SEG*DH];
__device__ float g_poolpart[PSPL][B_SEG*DH];
__device__ float g_msumpart[PSPL][B_SEG*D_EMB];
__device__ float g_outpart[8][B_SEG*D_EMB];
__device__ int   g_segstart[B_SEG+1];

// ---------------- helpers ----------------------------------------------------
__device__ __forceinline__ uint32_t smem_u32(const void* p){
    uint32_t a;
    asm("{ .reg .u64 t; cvta.to.shared.u64 t, %1; cvt.u32.u64 %0, t; }" : "=r"(a) : "l"(p));
    return a;
}
__device__ __forceinline__ void cpa16(uint32_t dst, const void* src){
    asm volatile("cp.async.cg.shared.global [%0], [%1], 16;\n" :: "r"(dst), "l"(src));
}
__device__ __forceinline__ void cpa_commit(){ asm volatile("cp.async.commit_group;\n" ::: "memory"); }
__device__ __forceinline__ void cpa_wait2(){ asm volatile("cp.async.wait_group 2;\n" ::: "memory"); }
__device__ __forceinline__ void cpa_wait1(){ asm volatile("cp.async.wait_group 1;\n" ::: "memory"); }
__device__ __forceinline__ void cpa_wait0(){ asm volatile("cp.async.wait_group 0;\n" ::: "memory"); }

__device__ __forceinline__ void ldm_x4(uint32_t* r, uint32_t addr){
    asm volatile("ldmatrix.sync.aligned.m8n8.x4.shared.b16 {%0,%1,%2,%3}, [%4];"
        : "=r"(r[0]),"=r"(r[1]),"=r"(r[2]),"=r"(r[3]) : "r"(addr));
}
__device__ __forceinline__ void mma_f16(float* d, const uint32_t* a, const uint32_t* b){
    asm volatile("mma.sync.aligned.m16n8k16.row.col.f32.f16.f16.f32 "
        "{%0,%1,%2,%3}, {%4,%5,%6,%7}, {%8,%9}, {%0,%1,%2,%3};"
        : "+f"(d[0]),"+f"(d[1]),"+f"(d[2]),"+f"(d[3])
        : "r"(a[0]),"r"(a[1]),"r"(a[2]),"r"(a[3]), "r"(b[0]),"r"(b[1]));
}

// ---------------- 1: fused prep: prefix + splitx + splitw ----------------------
// grid: blocks 0..16383 -> splitx rows; 16384..16447 -> splitw (64 blocks of
// 32x32 tiles arranged 64 = (A/32=64 a-tiles) x ... we need 64x32 tiles:
// A_DIM/32 * D_EMB/32 = 64*32 = 2048 blocks. Total grid = 16384/16? Use:
//   y=0: splitx, 4096 blocks of 4096 elems
//   y=1: splitw, 2048 blocks (32x32 tile each), 256 threads
//   y=2: block 0 thread 0 does prefix
__global__ __launch_bounds__(256) void k_prep(const float* __restrict__ x,
                                              const float* __restrict__ w1,
                                              const int* __restrict__ seg){
    if (blockIdx.y == 0){
        size_t i = ((size_t)blockIdx.x * 256 + threadIdx.x) * 4;
        float4 v = *(const float4*)(x + i);
        *(__half2*)&g_xh[i]   = __floats2half2_rn(v.x, v.y);
        *(__half2*)&g_xh[i+2] = __floats2half2_rn(v.z, v.w);
    } else if (blockIdx.x < 2048){
        __shared__ float t[32][33];
        const int a0 = (blockIdx.x & 63) * 32, k0 = (blockIdx.x >> 6) * 32;
        const int tx = threadIdx.x & 31, ty = threadIdx.x >> 5;  // (32, 8)
        #pragma unroll
        for (int i = 0; i < 4; i++)
            t[ty + i*8][tx] = w1[(size_t)(k0 + ty + i*8) * A_DIM + a0 + tx];
        __syncthreads();
        #pragma unroll
        for (int i = 0; i < 4; i++){
            int al = ty + i*8;
            float v = t[tx][al];
            __half h = __float2half_rn(v);
            g_w1h[(size_t)(a0 + al) * D_EMB + k0 + tx] = h;
            g_w1l[(size_t)(a0 + al) * D_EMB + k0 + tx] =
                __float2half_rn(v - __half2float(h));
        }
        if (blockIdx.x == 0 && threadIdx.x == 0){
            int acc = 0; g_segstart[0] = 0;
            for (int i = 0; i < B_SEG; i++){ acc += seg[i]; g_segstart[i+1] = acc; }
        }
    }
}

// ---------------- 2: fp16x2 MMA GEMM + fused relu@w2 epilogue ------------------
// R11 mainloop: CTA 128m x 128a, 8 warps (2x4), warp tile 64x32, K chunks of 32.
// 64B rows, XOR swizzle s(r)=(r>>1)&3. 4-stage cp.async, wait2, one sync/chunk,
// warps de-phased (kk order by warp parity), prefetch between the two k16 halves.
#define ROWB   64
#define ARR_SZ (128*ROWB)
#define STG_SZ (3*ARR_SZ)         // XH|WH|WL = 24576 B
#define NSTG   4
#define OFF_XH 0
#define OFF_WH (1*ARR_SZ)
#define OFF_WL (2*ARR_SZ)
#define OFF_C  0                            // union with stage buffers
#define C_LD   136
#define OFF_W2 (NSTG*STG_SZ)                // 98304
#define SM_TOT (OFF_W2 + 128*H_H*4)         // 102400

__device__ __forceinline__ uint32_t swz(int row, int j){
    return (uint32_t)(row * ROWB + ((j ^ ((row >> 1) & 3)) << 4));
}

__device__ __forceinline__ void load_chunk(uint32_t sbuf, int c, int m0, int a0){
    const int tid = threadIdx.x;
    const int row = tid >> 1;
    const int j0  = (tid & 1) * 2;
    const size_t xo = (size_t)(m0 + row) * D_EMB + c * 32;
    const size_t wo = (size_t)(a0 + row) * D_EMB + c * 32;
    #pragma unroll
    for (int j = j0; j < j0 + 2; j++){
        const uint32_t so = swz(row, j);
        cpa16(sbuf + OFF_XH + so, g_xh  + xo + j * 8);
        cpa16(sbuf + OFF_WH + so, g_w1h + wo + j * 8);
        cpa16(sbuf + OFF_WL + so, g_w1l + wo + j * 8);
    }
    cpa_commit();
}

struct LaneCtx { int a_row, a_jh, b_row, b_jh, wm, wn; };

__device__ __forceinline__ void do_k16(uint32_t base, const LaneCtx& L, int kk,
                                       float acc[4][4][4]){
    const int jb = kk * 2;
    uint32_t ah[4][4];
    #pragma unroll
    for (int mt = 0; mt < 4; mt++){
        int r = L.wm * 64 + mt * 16 + L.a_row;
        ldm_x4(ah[mt], base + OFF_XH + swz(r, jb + L.a_jh));
    }
    uint32_t bh[2][4], bl[2][4];
    #pragma unroll
    for (int np = 0; np < 2; np++){
        int r = L.wn * 32 + np * 16 + L.b_row;
        ldm_x4(bh[np], base + OFF_WH + swz(r, jb + L.b_jh));
    }
    #pragma unroll
    for (int np = 0; np < 2; np++){
        int r = L.wn * 32 + np * 16 + L.b_row;
        ldm_x4(bl[np], base + OFF_WL + swz(r, jb + L.b_jh));
    }
    #pragma unroll
    for (int mt = 0; mt < 4; mt++)
        #pragma unroll
        for (int nt = 0; nt < 4; nt++)
            mma_f16(acc[mt][nt], ah[mt], &bh[nt >> 1][(nt & 1) * 2]);
    #pragma unroll
    for (int mt = 0; mt < 4; mt++)
        #pragma unroll
        for (int nt = 0; nt < 4; nt++)
            mma_f16(acc[mt][nt], ah[mt], &bl[nt >> 1][(nt & 1) * 2]);
}

__global__ void __launch_bounds__(256, 2) k_mma1(const float* __restrict__ w2){
    extern __shared__ char smem[];
    const uint32_t sb = smem_u32(smem);
    float* Cs  = (float*)(smem + OFF_C);
    float* W2s = (float*)(smem + OFF_W2);
    const int tid = threadIdx.x;
    const int wid = tid >> 5, lane = tid & 31;
    const int grp = lane >> 2, t4 = lane & 3;
    const int m0 = blockIdx.x * 128;
    const int a0 = blockIdx.y * 128;
    const int kk0 = wid & 1;

    LaneCtx L;
    L.wm = wid >> 2; L.wn = wid & 3;
    L.a_row = (lane & 15);
    L.a_jh  = (lane >> 4);
    L.b_row = (lane & 7) + ((lane >> 4) << 3);
    L.b_jh  = ((lane >> 3) & 1);

    for (int i = tid; i < 128 * H_H; i += 256)
        W2s[i] = w2[(size_t)(a0 + (i >> 3)) * H_H + (i & 7)];

    float acc[4][4][4];
    #pragma unroll
    for (int mt = 0; mt < 4; mt++)
        #pragma unroll
        for (int nt = 0; nt < 4; nt++)
            #pragma unroll
            for (int j = 0; j < 4; j++) acc[mt][nt][j] = 0.f;

    load_chunk(sb + 0*STG_SZ, 0, m0, a0);
    load_chunk(sb + 1*STG_SZ, 1, m0, a0);
    load_chunk(sb + 2*STG_SZ, 2, m0, a0);

    uint32_t base = sb;
    for (int c = 0; c < 32; c++){
        if (c < 30) cpa_wait2(); else if (c == 30) cpa_wait1(); else cpa_wait0();
        __syncthreads();

        do_k16(base, L, kk0, acc);
        if (c + 3 < 32)
            load_chunk(sb + ((c + 3) % NSTG) * STG_SZ, c + 3, m0, a0);
        do_k16(base, L, kk0 ^ 1, acc);

        base = sb + ((c + 1) % NSTG) * STG_SZ;
    }
    __syncthreads();

    // relu(C) -> smem (union region)
    #pragma unroll
    for (int mt = 0; mt < 4; mt++)
        #pragma unroll
        for (int nt = 0; nt < 4; nt++){
            const int r0 = L.wm * 64 + mt * 16 + grp;
            const int c0 = L.wn * 32 + nt * 8 + t4 * 2;
            Cs[(r0    ) * C_LD + c0    ] = fmaxf(acc[mt][nt][0], 0.f);
            Cs[(r0    ) * C_LD + c0 + 1] = fmaxf(acc[mt][nt][1], 0.f);
            Cs[(r0 + 8) * C_LD + c0    ] = fmaxf(acc[mt][nt][2], 0.f);
            Cs[(r0 + 8) * C_LD + c0 + 1] = fmaxf(acc[mt][nt][3], 0.f);
        }
    __syncthreads();

    // h partial: relu(C)[128x128] @ w2slice[128x8], float4 C reads
    #pragma unroll
    for (int it = 0; it < 4; it++){
        const int idx = tid + it * 256;
        const int row = idx >> 3, h = idx & 7;
        float s = 0.f;
        #pragma unroll 4
        for (int cc = 0; cc < 128; cc += 4){
            float4 cv = *(const float4*)&Cs[row * C_LD + cc];
            s = fmaf(cv.x, W2s[(cc    ) * H_H + h], s);
            s = fmaf(cv.y, W2s[(cc + 1) * H_H + h], s);
            s = fmaf(cv.z, W2s[(cc + 2) * H_H + h], s);
            s = fmaf(cv.w, W2s[(cc + 3) * H_H + h], s);
        }
        g_hpart[blockIdx.y][(size_t)(m0 + row) * H_H + h] = s;
    }
}

// ---------------- 3a: parallel reduce of h partials ----------------------------
__global__ __launch_bounds__(256) void k_hred(){
    const int i = blockIdx.x * 256 + threadIdx.x;
    float v = 0.f;
    #pragma unroll
    for (int p = 0; p < NTA; p++) v += g_hpart[p][i];
    g_h[i] = v;
}

// ---------------- 3b: per-segment softmax --------------------------------------
__global__ __launch_bounds__(256) void k_softmax(){
    const int b = blockIdx.x, tid = threadIdx.x;
    const int start = g_segstart[b];
    const int len = g_segstart[b+1] - start;
    __shared__ float red[256 * H_H];
    __shared__ float mval[H_H], sval[H_H];

    float lm[H_H];
    #pragma unroll
    for (int h = 0; h < H_H; h++) lm[h] = -1e30f;
    for (int r = tid; r < len; r += 256){
        const int n = start + r;
        #pragma unroll
        for (int h = 0; h < H_H; h++)
            lm[h] = fmaxf(lm[h], g_h[(size_t)n*H_H + h]);
    }
    #pragma unroll
    for (int h = 0; h < H_H; h++) red[tid*H_H + h] = lm[h];
    __syncthreads();
    for (int off = 128; off > 0; off >>= 1){
        if (tid < off)
            #pragma unroll
            for (int h = 0; h < H_H; h++)
                red[tid*H_H+h] = fmaxf(red[tid*H_H+h], red[(tid+off)*H_H+h]);
        __syncthreads();
    }
    if (tid < H_H) mval[tid] = red[tid];
    __syncthreads();

    float ls[H_H];
    #pragma unroll
    for (int h = 0; h < H_H; h++) ls[h] = 0.f;
    for (int r = tid; r < len; r += 256){
        const int n = start + r;
        #pragma unroll
        for (int h = 0; h < H_H; h++) ls[h] += expf(g_h[(size_t)n*H_H+h] - mval[h]);
    }
    #pragma unroll
    for (int h = 0; h < H_H; h++) red[tid*H_H + h] = ls[h];
    __syncthreads();
    for (int off = 128; off > 0; off >>= 1){
        if (tid < off)
            #pragma unroll
            for (int h = 0; h < H_H; h++)
                red[tid*H_H+h] += red[(tid+off)*H_H+h];
        __syncthreads();
    }
    if (tid < H_H) sval[tid] = red[tid];
    __syncthreads();

    float inv[H_H];
    #pragma unroll
    for (int h = 0; h < H_H; h++) inv[h] = 1.f / sval[h];
    for (int r = tid; r < len; r += 256){
        const int n = start + r;
        #pragma unroll
        for (int h = 0; h < H_H; h++)
            g_attn[(size_t)n*H_H+h] = expf(g_h[(size_t)n*H_H+h] - mval[h]) * inv[h];
    }
}

// ---------------- 4: pooling (fp16 x, column pairs) -----------------------------
__global__ __launch_bounds__(256) void k_pool(){
    const int b = blockIdx.x;
    const int d0 = blockIdx.y * 512 + threadIdx.x * 2;
    const int chunk = blockIdx.z;
    const int start = g_segstart[b];
    const int len = g_segstart[b+1] - start;
    const int cl = (len + PSPL - 1) / PSPL;
    const int r0b = chunk * cl;
    const int r1b = min(len, r0b + cl);

    __shared__ float sat[32][H_H];
    float2 acc[H_H];
    #pragma unroll
    for (int h = 0; h < H_H; h++) acc[h] = make_float2(0.f, 0.f);
    float2 ssum = make_float2(0.f, 0.f);

    for (int r0 = r0b; r0 < r1b; r0 += 32){
        const int cnt = min(32, r1b - r0);
        if (threadIdx.x < cnt * H_H){
            const int rr = threadIdx.x >> 3, hh = threadIdx.x & 7;
            sat[rr][hh] = g_attn[(size_t)(start + r0 + rr) * H_H + hh];
        }
        __syncthreads();
        for (int rr = 0; rr < cnt; rr++){
            __half2 xv2 = *(const __half2*)&g_xh[(size_t)(start + r0 + rr) * D_EMB + d0];
            float2 xf = __half22float2(xv2);
            ssum.x += xf.x; ssum.y += xf.y;
            #pragma unroll
            for (int h = 0; h < H_H; h++){
                acc[h].x = fmaf(xf.x, sat[rr][h], acc[h].x);
                acc[h].y = fmaf(xf.y, sat[rr][h], acc[h].y);
            }
        }
        __syncthreads();
    }
    #pragma unroll
    for (int h = 0; h < H_H; h++){
        g_poolpart[chunk][(size_t)b * DH + d0 * H_H + h]       = acc[h].x;
        g_poolpart[chunk][(size_t)b * DH + (d0 + 1) * H_H + h] = acc[h].y;
    }
    g_msumpart[chunk][(size_t)b * D_EMB + d0]     = ssum.x;
    g_msumpart[chunk][(size_t)b * D_EMB + d0 + 1] = ssum.y;
}

// ---------------- 5: fused poolred + gram ---------------------------------------
// blocks 0..255: poolred; blocks 256..319: gram (one per segment)
__global__ __launch_bounds__(256) void k_poolred_gram(float* __restrict__ out){
    if (blockIdx.x < 256){
        const int i = blockIdx.x * 256 + threadIdx.x;
        const int b = i >> 10, d = i & 1023;
        float acc[H_H];
        #pragma unroll
        for (int h = 0; h < H_H; h++) acc[h] = 0.f;
        float s = 0.f;
        #pragma unroll
        for (int p = 0; p < PSPL; p++){
            #pragma unroll
            for (int h = 0; h < H_H; h++)
                acc[h] += g_poolpart[p][(size_t)b * DH + d * H_H + h];
            s += g_msumpart[p][(size_t)b * D_EMB + d];
        }
        #pragma unroll
        for (int h = 0; h < H_H; h++)
            g_obdh[(size_t)b * DH + d * H_H + h] = acc[h];
        const int len = g_segstart[b+1] - g_segstart[b];
        out[B_SEG * D_EMB + i] = s / (float)len;
    } else {
        const int b = blockIdx.x - 256;
        const int tid = threadIdx.x;
        const int pair = tid & 63, slice = tid >> 6;
        const int i = pair >> 3, j = pair & 7;
        const int start = g_segstart[b];
        const int len = g_segstart[b+1] - start;
        const int cl = (len + 3) >> 2;
        const int r0 = slice * cl;
        const int r1 = min(len, r0 + cl);
        float acc = 0.f;
        for (int r = r0; r < r1; r++){
            const float* a = &g_attn[(size_t)(start + r) * H_H];
            acc = fmaf(a[i], a[j], acc);
        }
        __shared__ float red[256];
        red[tid] = acc;
        __syncthreads();
        if (tid < 128) red[tid] += red[tid + 128];
        __syncthreads();
        if (tid < 64)
            out[2 * B_SEG * D_EMB + b * 64 + tid] = red[tid] + red[tid + 64];
    }
}

// ---------------- 6: post GEMM (64x1024x8192) -----------------------------------
__global__ __launch_bounds__(256) void k_post(const float* __restrict__ wp){
    __shared__ float As[16][72];
    __shared__ float Ws[16][72];
    const int tid = threadIdx.x;
    const int tx = tid & 15, ty = tid >> 4;
    const int j0 = blockIdx.x * 64;
    const int ks = blockIdx.y;
    const int kbase = ks * 1024;

    float acc[4][4];
    #pragma unroll
    for (int i = 0; i < 4; i++)
        #pragma unroll
        for (int j = 0; j < 4; j++) acc[i][j] = 0.f;

    for (int kc = 0; kc < 64; kc++){
        const int k0 = kbase + kc * 16;
        {
            const int row = tid >> 2, q = tid & 3;
            float4 v = *(const float4*)&g_obdh[(size_t)row * DH + k0 + q * 4];
            As[q*4+0][row] = v.x; As[q*4+1][row] = v.y;
            As[q*4+2][row] = v.z; As[q*4+3][row] = v.w;
        }
        {
            const int row = tid >> 4, q = tid & 15;
            float4 v = *(const float4*)&wp[(size_t)(k0 + row) * D_EMB + j0 + q * 4];
            *(float4*)&Ws[row][q * 4] = v;
        }
        __syncthreads();
        #pragma unroll
        for (int k = 0; k < 16; k++){
            float4 av = *(const float4*)&As[k][ty * 4];
            float4 wv = *(const float4*)&Ws[k][tx * 4];
            float ar[4] = {av.x, av.y, av.z, av.w};
            float wr[4] = {wv.x, wv.y, wv.z, wv.w};
            #pragma unroll
            for (int i = 0; i < 4; i++)
                #pragma unroll
                for (int j = 0; j < 4; j++)
                    acc[i][j] = fmaf(ar[i], wr[j], acc[i][j]);
        }
        __syncthreads();
    }
    #pragma unroll
    for (int i = 0; i < 4; i++)
        #pragma unroll
        for (int j = 0; j < 4; j++)
            g_outpart[ks][(size_t)(ty*4 + i) * D_EMB + j0 + tx*4 + j] = acc[i][j];
}

__global__ void k_redout(float* __restrict__ out){
    const int i = blockIdx.x * 256 + threadIdx.x;
    float s = 0.f;
    #pragma unroll
    for (int p = 0; p < 8; p++) s += g_outpart[p][i];
    out[i] = s;
}

// ---------------- launch ----------------------------------------------------------
extern "C" void kernel_launch(void* const* d_in, const int* in_sizes, int n_in,
                              void* d_out, int out_size)
{
    const float* x   = (const float*)d_in[0];
    const int*   seg = (const int*)  d_in[1];
    const float* w1  = (const float*)d_in[2];
    const float* w2  = (const float*)d_in[3];
    const float* wp  = (const float*)d_in[4];
    float* out = (float*)d_out;

    cudaFuncSetAttribute(k_mma1, cudaFuncAttributeMaxDynamicSharedMemorySize, SM_TOT);

    k_prep    <<<dim3(N_FR*D_EMB/1024, 2), 256>>>(x, w1, seg);
    k_mma1    <<<dim3(N_FR/128, NTA), 256, SM_TOT>>>(w2);
    k_hred    <<<N_FR*H_H/256, 256>>>();
    k_softmax <<<B_SEG, 256>>>();
    k_pool    <<<dim3(B_SEG, 2, PSPL), 256>>>();
    k_poolred_gram<<<256 + B_SEG, 256>>>(out);
    k_post    <<<dim3(16, 8), 256>>>(wp);
    k_redout  <<<B_SEG*D_EMB/256, 256>>>(out);
}

// round 14
// speedup vs baseline: 1.1888x; 1.0337x over previous
#include <cuda_runtime.h>
#include <cuda_fp16.h>
#include <math.h>
#include <stdint.h>

#define N_FR   16384
#define D_EMB  1024
#define A_DIM  2048
#define H_H    8
#define B_SEG  64
#define DH     (D_EMB*H_H)
#define NTA    16         // a-tiles of 128
#define PSPL   8          // pool row-splits

// ---------------- scratch ---------------------------------------------------
__device__ __align__(128) __half g_xh [N_FR*D_EMB];            // x in fp16
__device__ __align__(128) __half g_w1h[A_DIM*D_EMB];           // w1^T hi fp16
__device__ __align__(128) __half g_w1l[A_DIM*D_EMB];           // w1^T lo fp16
__device__ float g_hpart[NTA][N_FR*H_H];
__device__ float g_h[N_FR*H_H];
__device__ float g_attn[N_FR*H_H];
__device__ float g_obdh[B_SEG*DH];
__device__ float g_poolpart[PSPL][B_SEG*DH];
__device__ float g_msumpart[PSPL][B_SEG*D_EMB];
__device__ float g_outpart[8][B_SEG*D_EMB];
__device__ int   g_segstart[B_SEG+1];

// ---------------- helpers ----------------------------------------------------
__device__ __forceinline__ uint32_t smem_u32(const void* p){
    uint32_t a;
    asm("{ .reg .u64 t; cvta.to.shared.u64 t, %1; cvt.u32.u64 %0, t; }" : "=r"(a) : "l"(p));
    return a;
}
__device__ __forceinline__ void cpa16(uint32_t dst, const void* src){
    asm volatile("cp.async.cg.shared.global [%0], [%1], 16;\n" :: "r"(dst), "l"(src));
}
__device__ __forceinline__ void cpa_commit(){ asm volatile("cp.async.commit_group;\n" ::: "memory"); }
__device__ __forceinline__ void cpa_wait2(){ asm volatile("cp.async.wait_group 2;\n" ::: "memory"); }
__device__ __forceinline__ void cpa_wait1(){ asm volatile("cp.async.wait_group 1;\n" ::: "memory"); }
__device__ __forceinline__ void cpa_wait0(){ asm volatile("cp.async.wait_group 0;\n" ::: "memory"); }

__device__ __forceinline__ void ldm_x4(uint32_t* r, uint32_t addr){
    asm volatile("ldmatrix.sync.aligned.m8n8.x4.shared.b16 {%0,%1,%2,%3}, [%4];"
        : "=r"(r[0]),"=r"(r[1]),"=r"(r[2]),"=r"(r[3]) : "r"(addr));
}
__device__ __forceinline__ void mma_f16(float* d, const uint32_t* a, const uint32_t* b){
    asm volatile("mma.sync.aligned.m16n8k16.row.col.f32.f16.f16.f32 "
        "{%0,%1,%2,%3}, {%4,%5,%6,%7}, {%8,%9}, {%0,%1,%2,%3};"
        : "+f"(d[0]),"+f"(d[1]),"+f"(d[2]),"+f"(d[3])
        : "r"(a[0]),"r"(a[1]),"r"(a[2]),"r"(a[3]), "r"(b[0]),"r"(b[1]));
}

// ---------------- 1: fused prep: prefix + splitx + splitw ----------------------
__global__ __launch_bounds__(256) void k_prep(const float* __restrict__ x,
                                              const float* __restrict__ w1,
                                              const int* __restrict__ seg){
    if (blockIdx.y == 0){
        size_t i = ((size_t)blockIdx.x * 256 + threadIdx.x) * 4;
        float4 v = *(const float4*)(x + i);
        *(__half2*)&g_xh[i]   = __floats2half2_rn(v.x, v.y);
        *(__half2*)&g_xh[i+2] = __floats2half2_rn(v.z, v.w);
    } else if (blockIdx.x < 2048){
        __shared__ float t[32][33];
        const int a0 = (blockIdx.x & 63) * 32, k0 = (blockIdx.x >> 6) * 32;
        const int tx = threadIdx.x & 31, ty = threadIdx.x >> 5;  // (32, 8)
        #pragma unroll
        for (int i = 0; i < 4; i++)
            t[ty + i*8][tx] = w1[(size_t)(k0 + ty + i*8) * A_DIM + a0 + tx];
        __syncthreads();
        #pragma unroll
        for (int i = 0; i < 4; i++){
            int al = ty + i*8;
            float v = t[tx][al];
            __half h = __float2half_rn(v);
            g_w1h[(size_t)(a0 + al) * D_EMB + k0 + tx] = h;
            g_w1l[(size_t)(a0 + al) * D_EMB + k0 + tx] =
                __float2half_rn(v - __half2float(h));
        }
        if (blockIdx.x == 0 && threadIdx.x == 0){
            int acc = 0; g_segstart[0] = 0;
            for (int i = 0; i < B_SEG; i++){ acc += seg[i]; g_segstart[i+1] = acc; }
        }
    }
}

// ---------------- 2: fp16x2 MMA GEMM + fused relu@w2 epilogue ------------------
// R11 mainloop (locked): CTA 128x128, 8 warps (2x4), warp tile 64x32, K=32
// chunks, 4-stage cp.async (wait2), one sync/chunk, warp de-phasing, prefetch
// between halves. R14: bl LDSM deferred until after the bh MMA block.
#define ROWB   64
#define ARR_SZ (128*ROWB)
#define STG_SZ (3*ARR_SZ)         // XH|WH|WL = 24576 B
#define NSTG   4
#define OFF_XH 0
#define OFF_WH (1*ARR_SZ)
#define OFF_WL (2*ARR_SZ)
#define OFF_C  0                            // union with stage buffers
#define C_LD   136
#define OFF_W2 (NSTG*STG_SZ)                // 98304
#define SM_TOT (OFF_W2 + 128*H_H*4)         // 102400

__device__ __forceinline__ uint32_t swz(int row, int j){
    return (uint32_t)(row * ROWB + ((j ^ ((row >> 1) & 3)) << 4));
}

__device__ __forceinline__ void load_chunk(uint32_t sbuf, int c, int m0, int a0){
    const int tid = threadIdx.x;
    const int row = tid >> 1;
    const int j0  = (tid & 1) * 2;
    const size_t xo = (size_t)(m0 + row) * D_EMB + c * 32;
    const size_t wo = (size_t)(a0 + row) * D_EMB + c * 32;
    #pragma unroll
    for (int j = j0; j < j0 + 2; j++){
        const uint32_t so = swz(row, j);
        cpa16(sbuf + OFF_XH + so, g_xh  + xo + j * 8);
        cpa16(sbuf + OFF_WH + so, g_w1h + wo + j * 8);
        cpa16(sbuf + OFF_WL + so, g_w1l + wo + j * 8);
    }
    cpa_commit();
}

struct LaneCtx { int a_row, a_jh, b_row, b_jh, wm, wn; };

__device__ __forceinline__ void do_k16(uint32_t base, const LaneCtx& L, int kk,
                                       float acc[4][4][4]){
    const int jb = kk * 2;
    uint32_t ah[4][4];
    #pragma unroll
    for (int mt = 0; mt < 4; mt++){
        int r = L.wm * 64 + mt * 16 + L.a_row;
        ldm_x4(ah[mt], base + OFF_XH + swz(r, jb + L.a_jh));
    }
    uint32_t bh[2][4];
    #pragma unroll
    for (int np = 0; np < 2; np++){
        int r = L.wn * 32 + np * 16 + L.b_row;
        ldm_x4(bh[np], base + OFF_WH + swz(r, jb + L.b_jh));
    }
    #pragma unroll
    for (int mt = 0; mt < 4; mt++)
        #pragma unroll
        for (int nt = 0; nt < 4; nt++)
            mma_f16(acc[mt][nt], ah[mt], &bh[nt >> 1][(nt & 1) * 2]);
    // bl loads deferred: overlap the bh MMA run, shorter dependency head
    uint32_t bl[2][4];
    #pragma unroll
    for (int np = 0; np < 2; np++){
        int r = L.wn * 32 + np * 16 + L.b_row;
        ldm_x4(bl[np], base + OFF_WL + swz(r, jb + L.b_jh));
    }
    #pragma unroll
    for (int mt = 0; mt < 4; mt++)
        #pragma unroll
        for (int nt = 0; nt < 4; nt++)
            mma_f16(acc[mt][nt], ah[mt], &bl[nt >> 1][(nt & 1) * 2]);
}

__global__ void __launch_bounds__(256, 2) k_mma1(const float* __restrict__ w2){
    extern __shared__ char smem[];
    const uint32_t sb = smem_u32(smem);
    float* Cs  = (float*)(smem + OFF_C);
    float* W2s = (float*)(smem + OFF_W2);
    const int tid = threadIdx.x;
    const int wid = tid >> 5, lane = tid & 31;
    const int grp = lane >> 2, t4 = lane & 3;
    const int m0 = blockIdx.x * 128;
    const int a0 = blockIdx.y * 128;
    const int kk0 = wid & 1;

    LaneCtx L;
    L.wm = wid >> 2; L.wn = wid & 3;
    L.a_row = (lane & 15);
    L.a_jh  = (lane >> 4);
    L.b_row = (lane & 7) + ((lane >> 4) << 3);
    L.b_jh  = ((lane >> 3) & 1);

    for (int i = tid; i < 128 * H_H; i += 256)
        W2s[i] = w2[(size_t)(a0 + (i >> 3)) * H_H + (i & 7)];

    float acc[4][4][4];
    #pragma unroll
    for (int mt = 0; mt < 4; mt++)
        #pragma unroll
        for (int nt = 0; nt < 4; nt++)
            #pragma unroll
            for (int j = 0; j < 4; j++) acc[mt][nt][j] = 0.f;

    load_chunk(sb + 0*STG_SZ, 0, m0, a0);
    load_chunk(sb + 1*STG_SZ, 1, m0, a0);
    load_chunk(sb + 2*STG_SZ, 2, m0, a0);

    uint32_t base = sb;
    for (int c = 0; c < 32; c++){
        if (c < 30) cpa_wait2(); else if (c == 30) cpa_wait1(); else cpa_wait0();
        __syncthreads();

        do_k16(base, L, kk0, acc);
        if (c + 3 < 32)
            load_chunk(sb + ((c + 3) % NSTG) * STG_SZ, c + 3, m0, a0);
        do_k16(base, L, kk0 ^ 1, acc);

        base = sb + ((c + 1) % NSTG) * STG_SZ;
    }
    __syncthreads();

    // relu(C) -> smem (union region)
    #pragma unroll
    for (int mt = 0; mt < 4; mt++)
        #pragma unroll
        for (int nt = 0; nt < 4; nt++){
            const int r0 = L.wm * 64 + mt * 16 + grp;
            const int c0 = L.wn * 32 + nt * 8 + t4 * 2;
            Cs[(r0    ) * C_LD + c0    ] = fmaxf(acc[mt][nt][0], 0.f);
            Cs[(r0    ) * C_LD + c0 + 1] = fmaxf(acc[mt][nt][1], 0.f);
            Cs[(r0 + 8) * C_LD + c0    ] = fmaxf(acc[mt][nt][2], 0.f);
            Cs[(r0 + 8) * C_LD + c0 + 1] = fmaxf(acc[mt][nt][3], 0.f);
        }
    __syncthreads();

    // h partial: relu(C)[128x128] @ w2slice[128x8], float4 C reads
    #pragma unroll
    for (int it = 0; it < 4; it++){
        const int idx = tid + it * 256;
        const int row = idx >> 3, h = idx & 7;
        float s = 0.f;
        #pragma unroll 4
        for (int cc = 0; cc < 128; cc += 4){
            float4 cv = *(const float4*)&Cs[row * C_LD + cc];
            s = fmaf(cv.x, W2s[(cc    ) * H_H + h], s);
            s = fmaf(cv.y, W2s[(cc + 1) * H_H + h], s);
            s = fmaf(cv.z, W2s[(cc + 2) * H_H + h], s);
            s = fmaf(cv.w, W2s[(cc + 3) * H_H + h], s);
        }
        g_hpart[blockIdx.y][(size_t)(m0 + row) * H_H + h] = s;
    }
}

// ---------------- 3a: parallel reduce of h partials ----------------------------
__global__ __launch_bounds__(256) void k_hred(){
    const int i = blockIdx.x * 256 + threadIdx.x;
    float v = 0.f;
    #pragma unroll
    for (int p = 0; p < NTA; p++) v += g_hpart[p][i];
    g_h[i] = v;
}

// ---------------- 3b: per-segment softmax --------------------------------------
__global__ __launch_bounds__(256) void k_softmax(){
    const int b = blockIdx.x, tid = threadIdx.x;
    const int start = g_segstart[b];
    const int len = g_segstart[b+1] - start;
    __shared__ float red[256 * H_H];
    __shared__ float mval[H_H], sval[H_H];

    float lm[H_H];
    #pragma unroll
    for (int h = 0; h < H_H; h++) lm[h] = -1e30f;
    for (int r = tid; r < len; r += 256){
        const int n = start + r;
        #pragma unroll
        for (int h = 0; h < H_H; h++)
            lm[h] = fmaxf(lm[h], g_h[(size_t)n*H_H + h]);
    }
    #pragma unroll
    for (int h = 0; h < H_H; h++) red[tid*H_H + h] = lm[h];
    __syncthreads();
    for (int off = 128; off > 0; off >>= 1){
        if (tid < off)
            #pragma unroll
            for (int h = 0; h < H_H; h++)
                red[tid*H_H+h] = fmaxf(red[tid*H_H+h], red[(tid+off)*H_H+h]);
        __syncthreads();
    }
    if (tid < H_H) mval[tid] = red[tid];
    __syncthreads();

    float ls[H_H];
    #pragma unroll
    for (int h = 0; h < H_H; h++) ls[h] = 0.f;
    for (int r = tid; r < len; r += 256){
        const int n = start + r;
        #pragma unroll
        for (int h = 0; h < H_H; h++) ls[h] += expf(g_h[(size_t)n*H_H+h] - mval[h]);
    }
    #pragma unroll
    for (int h = 0; h < H_H; h++) red[tid*H_H + h] = ls[h];
    __syncthreads();
    for (int off = 128; off > 0; off >>= 1){
        if (tid < off)
            #pragma unroll
            for (int h = 0; h < H_H; h++)
                red[tid*H_H+h] += red[(tid+off)*H_H+h];
        __syncthreads();
    }
    if (tid < H_H) sval[tid] = red[tid];
    __syncthreads();

    float inv[H_H];
    #pragma unroll
    for (int h = 0; h < H_H; h++) inv[h] = 1.f / sval[h];
    for (int r = tid; r < len; r += 256){
        const int n = start + r;
        #pragma unroll
        for (int h = 0; h < H_H; h++)
            g_attn[(size_t)n*H_H+h] = expf(g_h[(size_t)n*H_H+h] - mval[h]) * inv[h];
    }
}

// ---------------- 4: pooling (fp16 x, column pairs) -----------------------------
__global__ __launch_bounds__(256) void k_pool(){
    const int b = blockIdx.x;
    const int d0 = blockIdx.y * 512 + threadIdx.x * 2;
    const int chunk = blockIdx.z;
    const int start = g_segstart[b];
    const int len = g_segstart[b+1] - start;
    const int cl = (len + PSPL - 1) / PSPL;
    const int r0b = chunk * cl;
    const int r1b = min(len, r0b + cl);

    __shared__ float sat[32][H_H];
    float2 acc[H_H];
    #pragma unroll
    for (int h = 0; h < H_H; h++) acc[h] = make_float2(0.f, 0.f);
    float2 ssum = make_float2(0.f, 0.f);

    for (int r0 = r0b; r0 < r1b; r0 += 32){
        const int cnt = min(32, r1b - r0);
        if (threadIdx.x < cnt * H_H){
            const int rr = threadIdx.x >> 3, hh = threadIdx.x & 7;
            sat[rr][hh] = g_attn[(size_t)(start + r0 + rr) * H_H + hh];
        }
        __syncthreads();
        for (int rr = 0; rr < cnt; rr++){
            __half2 xv2 = *(const __half2*)&g_xh[(size_t)(start + r0 + rr) * D_EMB + d0];
            float2 xf = __half22float2(xv2);
            ssum.x += xf.x; ssum.y += xf.y;
            #pragma unroll
            for (int h = 0; h < H_H; h++){
                acc[h].x = fmaf(xf.x, sat[rr][h], acc[h].x);
                acc[h].y = fmaf(xf.y, sat[rr][h], acc[h].y);
            }
        }
        __syncthreads();
    }
    #pragma unroll
    for (int h = 0; h < H_H; h++){
        g_poolpart[chunk][(size_t)b * DH + d0 * H_H + h]       = acc[h].x;
        g_poolpart[chunk][(size_t)b * DH + (d0 + 1) * H_H + h] = acc[h].y;
    }
    g_msumpart[chunk][(size_t)b * D_EMB + d0]     = ssum.x;
    g_msumpart[chunk][(size_t)b * D_EMB + d0 + 1] = ssum.y;
}

// ---------------- 5: fused poolred + gram ---------------------------------------
__global__ __launch_bounds__(256) void k_poolred_gram(float* __restrict__ out){
    if (blockIdx.x < 256){
        const int i = blockIdx.x * 256 + threadIdx.x;
        const int b = i >> 10, d = i & 1023;
        float acc[H_H];
        #pragma unroll
        for (int h = 0; h < H_H; h++) acc[h] = 0.f;
        float s = 0.f;
        #pragma unroll
        for (int p = 0; p < PSPL; p++){
            #pragma unroll
            for (int h = 0; h < H_H; h++)
                acc[h] += g_poolpart[p][(size_t)b * DH + d * H_H + h];
            s += g_msumpart[p][(size_t)b * D_EMB + d];
        }
        #pragma unroll
        for (int h = 0; h < H_H; h++)
            g_obdh[(size_t)b * DH + d * H_H + h] = acc[h];
        const int len = g_segstart[b+1] - g_segstart[b];
        out[B_SEG * D_EMB + i] = s / (float)len;
    } else {
        const int b = blockIdx.x - 256;
        const int tid = threadIdx.x;
        const int pair = tid & 63, slice = tid >> 6;
        const int i = pair >> 3, j = pair & 7;
        const int start = g_segstart[b];
        const int len = g_segstart[b+1] - start;
        const int cl = (len + 3) >> 2;
        const int r0 = slice * cl;
        const int r1 = min(len, r0 + cl);
        float acc = 0.f;
        for (int r = r0; r < r1; r++){
            const float* a = &g_attn[(size_t)(start + r) * H_H];
            acc = fmaf(a[i], a[j], acc);
        }
        __shared__ float red[256];
        red[tid] = acc;
        __syncthreads();
        if (tid < 128) red[tid] += red[tid + 128];
        __syncthreads();
        if (tid < 64)
            out[2 * B_SEG * D_EMB + b * 64 + tid] = red[tid] + red[tid + 64];
    }
}

// ---------------- 6: post GEMM (64x1024x8192) -----------------------------------
__global__ __launch_bounds__(256) void k_post(const float* __restrict__ wp){
    __shared__ float As[16][72];
    __shared__ float Ws[16][72];
    const int tid = threadIdx.x;
    const int tx = tid & 15, ty = tid >> 4;
    const int j0 = blockIdx.x * 64;
    const int ks = blockIdx.y;
    const int kbase = ks * 1024;

    float acc[4][4];
    #pragma unroll
    for (int i = 0; i < 4; i++)
        #pragma unroll
        for (int j = 0; j < 4; j++) acc[i][j] = 0.f;

    for (int kc = 0; kc < 64; kc++){
        const int k0 = kbase + kc * 16;
        {
            const int row = tid >> 2, q = tid & 3;
            float4 v = *(const float4*)&g_obdh[(size_t)row * DH + k0 + q * 4];
            As[q*4+0][row] = v.x; As[q*4+1][row] = v.y;
            As[q*4+2][row] = v.z; As[q*4+3][row] = v.w;
        }
        {
            const int row = tid >> 4, q = tid & 15;
            float4 v = *(const float4*)&wp[(size_t)(k0 + row) * D_EMB + j0 + q * 4];
            *(float4*)&Ws[row][q * 4] = v;
        }
        __syncthreads();
        #pragma unroll
        for (int k = 0; k < 16; k++){
            float4 av = *(const float4*)&As[k][ty * 4];
            float4 wv = *(const float4*)&Ws[k][tx * 4];
            float ar[4] = {av.x, av.y, av.z, av.w};
            float wr[4] = {wv.x, wv.y, wv.z, wv.w};
            #pragma unroll
            for (int i = 0; i < 4; i++)
                #pragma unroll
                for (int j = 0; j < 4; j++)
                    acc[i][j] = fmaf(ar[i], wr[j], acc[i][j]);
        }
        __syncthreads();
    }
    #pragma unroll
    for (int i = 0; i < 4; i++)
        #pragma unroll
        for (int j = 0; j < 4; j++)
            g_outpart[ks][(size_t)(ty*4 + i) * D_EMB + j0 + tx*4 + j] = acc[i][j];
}

__global__ void k_redout(float* __restrict__ out){
    const int i = blockIdx.x * 256 + threadIdx.x;
    float s = 0.f;
    #pragma unroll
    for (int p = 0; p < 8; p++) s += g_outpart[p][i];
    out[i] = s;
}

// ---------------- launch ----------------------------------------------------------
extern "C" void kernel_launch(void* const* d_in, const int* in_sizes, int n_in,
                              void* d_out, int out_size)
{
    const float* x   = (const float*)d_in[0];
    const int*   seg = (const int*)  d_in[1];
    const float* w1  = (const float*)d_in[2];
    const float* w2  = (const float*)d_in[3];
    const float* wp  = (const float*)d_in[4];
    float* out = (float*)d_out;

    cudaFuncSetAttribute(k_mma1, cudaFuncAttributeMaxDynamicSharedMemorySize, SM_TOT);

    k_prep    <<<dim3(N_FR*D_EMB/1024, 2), 256>>>(x, w1, seg);
    k_mma1    <<<dim3(N_FR/128, NTA), 256, SM_TOT>>>(w2);
    k_hred    <<<N_FR*H_H/256, 256>>>();
    k_softmax <<<B_SEG, 256>>>();
    k_pool    <<<dim3(B_SEG, 2, PSPL), 256>>>();
    k_poolred_gram<<<256 + B_SEG, 256>>>(out);
    k_post    <<<dim3(16, 8), 256>>>(wp);
    k_redout  <<<B_SEG*D_EMB/256, 256>>>(out);
}